// round 14
// baseline (speedup 1.0000x reference)
#include <cuda_runtime.h>
#include <cuda_fp16.h>
#include <cstdint>

#define M_NODES 10000
#define K_IN    512
#define N_HID   512
#define N_EDGES 160000

// Scratch (no allocations allowed)
__device__ __half g_xfts_h[M_NODES * N_HID];   // fp16 x_fts (L2-resident, 10 MB)
__device__ int    g_rowptr[M_NODES + 1];

// ---------------------------------------------------------------------------
// Tensor-core GEMM (mma.sync fp16), in-kernel A and B fp32->fp16 conversion,
// plus rowptr scatter in the prologue (replaces the prep kernel).
// CTA 128x128, BK=32, 256 threads = 8 warps (2m x 4n), warp tile 64x32.
// Double-buffered smem, register prefetch distance 2 for both operands.
// ---------------------------------------------------------------------------
#define BM 128
#define BN 128
#define BK 32
#define KSTRIDE 40
#define A_E      0
#define B_E      5120
#define STAGE_E  10240
#define SMEM_BYTES (2 * STAGE_E * 2)      // 40960

#define LDSM_X4(r0, r1, r2, r3, addr) \
    asm volatile("ldmatrix.sync.aligned.m8n8.x4.shared.b16 {%0,%1,%2,%3}, [%4];" \
                 : "=r"(r0), "=r"(r1), "=r"(r2), "=r"(r3) : "r"(addr))

#define STS128(addr, r0, r1, r2, r3) \
    asm volatile("st.shared.v4.b32 [%0], {%1,%2,%3,%4};" \
                 :: "r"(addr), "r"(r0), "r"(r1), "r"(r2), "r"(r3) : "memory")

__device__ __forceinline__ void mma_f16(float c[4], const uint32_t a[4],
                                        const uint32_t b[2])
{
    asm volatile(
        "mma.sync.aligned.m16n8k16.row.col.f32.f16.f16.f32 "
        "{%0,%1,%2,%3}, {%4,%5,%6,%7}, {%8,%9}, {%0,%1,%2,%3};\n"
        : "+f"(c[0]), "+f"(c[1]), "+f"(c[2]), "+f"(c[3])
        : "r"(a[0]), "r"(a[1]), "r"(a[2]), "r"(a[3]), "r"(b[0]), "r"(b[1]));
}

__device__ __forceinline__ uint32_t pack_h2(float a, float b)
{
    __half2 t = __floats2half2_rn(a, b);
    return *reinterpret_cast<uint32_t*>(&t);
}

__global__ __launch_bounds__(256, 2) void gemm_tc_kernel(
    const float* __restrict__ X,
    const float* __restrict__ W,
    const int* __restrict__ adj_row)
{
    extern __shared__ __half smem[];
    const int tid  = threadIdx.x;
    const int lane = tid & 31;
    const int wid  = tid >> 5;
    const int wm   = (wid & 1) * 64;
    const int wn   = (wid >> 1) * 32;
    const int m0   = blockIdx.y * BM;
    const int n0   = blockIdx.x * BN;
    const int grp  = lane >> 2;
    const int tig  = lane & 3;

    // --- rowptr scatter (replaces prep): 2 edge-slots per thread ---
    {
        int gtid = (blockIdx.y * 4 + blockIdx.x) * 256 + tid;   // 0..80895
#pragma unroll
        for (int s = 0; s < 2; s++) {
            int e = gtid * 2 + s;
            if (e <= N_EDGES) {
                int prev = (e == 0) ? -1 : __ldg(&adj_row[e - 1]);
                int cur  = (e == N_EDGES) ? M_NODES : __ldg(&adj_row[e]);
                for (int r = prev + 1; r <= cur; r++)
                    g_rowptr[r] = e;
            }
        }
    }

    const uint32_t smem_u32 = (uint32_t)__cvta_generic_to_shared(smem);

    float acc[4][4][4];
#pragma unroll
    for (int mi = 0; mi < 4; mi++)
#pragma unroll
        for (int ni = 0; ni < 4; ni++)
#pragma unroll
            for (int q = 0; q < 4; q++) acc[mi][ni][q] = 0.f;

    // --- loaders: thread -> (row = tid>>1, half = tid&1), 16 fp32 each ---
    const int rowL  = tid >> 1;           // 0..127
    const int halfL = tid & 1;
    int gmA = m0 + rowL;
    if (gmA >= M_NODES) gmA = 0;          // clamp; epilogue discards
    const float* Xrow = X + (size_t)gmA * K_IN + halfL * 16;
    const float* Wrow = W + (size_t)(n0 + rowL) * K_IN + halfL * 16;  // n0+rowL < 512

    auto ldg4 = [&](const float* base, int k0, float4 v[4]) {
        const float4* p = reinterpret_cast<const float4*>(base + k0);
        v[0] = __ldg(p);
        v[1] = __ldg(p + 1);
        v[2] = __ldg(p + 2);
        v[3] = __ldg(p + 3);
    };

    auto sts4 = [&](int buf, int region, const float4 v[4]) {
        uint32_t h[8];
#pragma unroll
        for (int j = 0; j < 4; j++) {
            h[2 * j]     = pack_h2(v[j].x, v[j].y);
            h[2 * j + 1] = pack_h2(v[j].z, v[j].w);
        }
        uint32_t base = smem_u32 +
            (uint32_t)(buf * STAGE_E + region + rowL * KSTRIDE + halfL * 16) * 2;
        STS128(base,      h[0], h[1], h[2], h[3]);
        STS128(base + 16, h[4], h[5], h[6], h[7]);
    };

    // --- prologue ---
    float4 av[4], bv[4];
    ldg4(Xrow, 0, av);
    ldg4(Wrow, 0, bv);
    sts4(0, A_E, av);
    sts4(0, B_E, bv);
    ldg4(Xrow, BK, av);
    ldg4(Wrow, BK, bv);

    const int a_row = wm + ((lane >> 3) & 1) * 8 + (lane & 7);
    const int a_seg = (lane >> 4) * 8;
    const int b_row = wn + (lane >> 4) * 8 + (lane & 7);
    const int b_seg = ((lane >> 3) & 1) * 8;

    const int NT = K_IN / BK;             // 16
    for (int t = 0; t < NT; t++) {
        __syncthreads();                  // makes sts(t) visible; frees buf (t+1)&1

        if (t + 1 < NT) {
            sts4((t + 1) & 1, A_E, av);
            sts4((t + 1) & 1, B_E, bv);
            if (t + 2 < NT) {
                ldg4(Xrow, (t + 2) * BK, av);
                ldg4(Wrow, (t + 2) * BK, bv);
            }
        }

        const uint32_t sbase = smem_u32 + (uint32_t)((t & 1) * STAGE_E) * 2;

#pragma unroll
        for (int ks = 0; ks < 2; ks++) {
            const int kcol = ks * 16;

            uint32_t a[4][4];
#pragma unroll
            for (int mi = 0; mi < 4; mi++) {
                uint32_t addr = sbase + (uint32_t)((a_row + mi * 16) * KSTRIDE + a_seg + kcol) * 2;
                LDSM_X4(a[mi][0], a[mi][1], a[mi][2], a[mi][3], addr);
            }
            uint32_t b[4][2];
#pragma unroll
            for (int njp = 0; njp < 2; njp++) {
                uint32_t addr = sbase + (uint32_t)(B_E + (b_row + njp * 16) * KSTRIDE + b_seg + kcol) * 2;
                LDSM_X4(b[njp * 2][0], b[njp * 2][1],
                        b[njp * 2 + 1][0], b[njp * 2 + 1][1], addr);
            }
#pragma unroll
            for (int mi = 0; mi < 4; mi++)
#pragma unroll
                for (int nj = 0; nj < 4; nj++)
                    mma_f16(acc[mi][nj], a[mi], b[nj]);
        }
    }

    // --- epilogue: fp32 acc -> fp16 x_fts ---
#pragma unroll
    for (int mi = 0; mi < 4; mi++) {
        int gm = m0 + wm + mi * 16 + grp;
#pragma unroll
        for (int nj = 0; nj < 4; nj++) {
            int gn = n0 + wn + nj * 8 + tig * 2;
            if (gm < M_NODES) {
                __half2 h = __float22half2_rn(make_float2(acc[mi][nj][0], acc[mi][nj][1]));
                *reinterpret_cast<__half2*>(&g_xfts_h[(size_t)gm * N_HID + gn]) = h;
            }
            if (gm + 8 < M_NODES) {
                __half2 h = __float22half2_rn(make_float2(acc[mi][nj][2], acc[mi][nj][3]));
                *reinterpret_cast<__half2*>(&g_xfts_h[(size_t)(gm + 8) * N_HID + gn]) = h;
            }
        }
    }
}

// ---------------------------------------------------------------------------
// SPMM + bias + PReLU: 2 rows/CTA, 64 threads/row, one LDG.128 per edge-thread.
// ---------------------------------------------------------------------------
__global__ __launch_bounds__(128) void spmm_bias_prelu_kernel(
    const float* __restrict__ adj_vals,
    const int* __restrict__ adj_col,
    const float* __restrict__ bias,
    const float* __restrict__ prelu_a,
    float* __restrict__ out)
{
    const int sub = threadIdx.x >> 6;
    const int lt  = threadIdx.x & 63;
    const int r   = blockIdx.x * 2 + sub;
    const int c   = lt * 8;
    const int start = g_rowptr[r];
    const int end   = g_rowptr[r + 1];

    float acc[4][8];
#pragma unroll
    for (int q = 0; q < 4; q++)
#pragma unroll
        for (int j = 0; j < 8; j++) acc[q][j] = 0.f;

    auto gather = [&](int e, float f[8]) {
        const int col = __ldg(&adj_col[e]);
        uint4 u = __ldg(reinterpret_cast<const uint4*>(
            &g_xfts_h[(size_t)col * N_HID + c]));
        float2 p0 = __half22float2(*reinterpret_cast<__half2*>(&u.x));
        float2 p1 = __half22float2(*reinterpret_cast<__half2*>(&u.y));
        float2 p2 = __half22float2(*reinterpret_cast<__half2*>(&u.z));
        float2 p3 = __half22float2(*reinterpret_cast<__half2*>(&u.w));
        f[0] = p0.x; f[1] = p0.y; f[2] = p1.x; f[3] = p1.y;
        f[4] = p2.x; f[5] = p2.y; f[6] = p3.x; f[7] = p3.y;
    };

    int e = start;
    for (; e + 3 < end; e += 4) {
        float v[4];
#pragma unroll
        for (int q = 0; q < 4; q++) v[q] = __ldg(&adj_vals[e + q]);
        float f[4][8];
#pragma unroll
        for (int q = 0; q < 4; q++) gather(e + q, f[q]);
#pragma unroll
        for (int q = 0; q < 4; q++)
#pragma unroll
            for (int j = 0; j < 8; j++)
                acc[q][j] += v[q] * f[q][j];
    }
    for (; e < end; e++) {
        float v0 = __ldg(&adj_vals[e]);
        float f[8];
        gather(e, f);
#pragma unroll
        for (int j = 0; j < 8; j++) acc[0][j] += v0 * f[j];
    }

    const float4 b0 = *reinterpret_cast<const float4*>(&bias[c]);
    const float4 b1 = *reinterpret_cast<const float4*>(&bias[c + 4]);
    const float a = *prelu_a;
    float o[8];
#pragma unroll
    for (int j = 0; j < 8; j++)
        o[j] = (acc[0][j] + acc[1][j]) + (acc[2][j] + acc[3][j]);
    o[0] += b0.x; o[1] += b0.y; o[2] += b0.z; o[3] += b0.w;
    o[4] += b1.x; o[5] += b1.y; o[6] += b1.z; o[7] += b1.w;
#pragma unroll
    for (int j = 0; j < 8; j++)
        o[j] = (o[j] >= 0.f) ? o[j] : a * o[j];

    float* dst = &out[(size_t)r * N_HID + c];
    *reinterpret_cast<float4*>(dst)     = make_float4(o[0], o[1], o[2], o[3]);
    *reinterpret_cast<float4*>(dst + 4) = make_float4(o[4], o[5], o[6], o[7]);
}

extern "C" void kernel_launch(void* const* d_in, const int* in_sizes, int n_in,
                              void* d_out, int out_size)
{
    const float* x        = (const float*)d_in[0];
    const float* fc_w     = (const float*)d_in[1];
    const float* bias     = (const float*)d_in[2];
    const float* prelu_a  = (const float*)d_in[3];
    const float* adj_vals = (const float*)d_in[4];
    const int*   adj_row  = (const int*)d_in[5];
    const int*   adj_col  = (const int*)d_in[6];
    float*       out      = (float*)d_out;

    cudaFuncSetAttribute(gemm_tc_kernel,
                         cudaFuncAttributeMaxDynamicSharedMemorySize, SMEM_BYTES);

    dim3 ggrid(N_HID / BN, (M_NODES + BM - 1) / BM);   // 4 x 79
    gemm_tc_kernel<<<ggrid, 256, SMEM_BYTES>>>(x, fc_w, adj_row);

    spmm_bias_prelu_kernel<<<M_NODES / 2, 128>>>(adj_vals, adj_col, bias, prelu_a, out);
}

// round 15
// speedup vs baseline: 1.2333x; 1.2333x over previous
#include <cuda_runtime.h>
#include <cuda_fp16.h>
#include <cstdint>

#define M_NODES 10000
#define K_IN    512
#define N_HID   512
#define N_EDGES 160000

// Scratch (no allocations allowed)
__device__ __half g_xfts_h[M_NODES * N_HID];   // fp16 x_fts (L2-resident, 10 MB)
__device__ __half g_wh[N_HID * K_IN];          // fp16 weights
__device__ int    g_rowptr[M_NODES + 1];

// ---------------------------------------------------------------------------
// Prep: convert W fp32 -> fp16, rowptr via edge-parallel scatter.
// ---------------------------------------------------------------------------
#define WBLK 32
#define RPBLK 626

__global__ __launch_bounds__(256) void prep_kernel(
    const float* __restrict__ fc_w,
    const int* __restrict__ adj_row)
{
    const int b = blockIdx.x;
    const int t = threadIdx.x;
    if (b < WBLK) {
        const int i0 = b * 2048 + t;
        float4 v[8];
#pragma unroll
        for (int k = 0; k < 8; k++)
            v[k] = reinterpret_cast<const float4*>(fc_w)[i0 + k * 256];
#pragma unroll
        for (int k = 0; k < 8; k++) {
            int i = i0 + k * 256;
            __half2 h0 = __floats2half2_rn(v[k].x, v[k].y);
            __half2 h1 = __floats2half2_rn(v[k].z, v[k].w);
            reinterpret_cast<__half2*>(g_wh)[2 * i]     = h0;
            reinterpret_cast<__half2*>(g_wh)[2 * i + 1] = h1;
        }
    } else {
        int e = (b - WBLK) * 256 + t;
        if (e > N_EDGES) return;
        int prev = (e == 0) ? -1 : adj_row[e - 1];
        int cur  = (e == N_EDGES) ? M_NODES : adj_row[e];
        for (int r = prev + 1; r <= cur; r++)
            g_rowptr[r] = e;
    }
}

// ---------------------------------------------------------------------------
// Tensor-core GEMM (mma.sync fp16), in-kernel A conversion.  (R13 config)
// CTA 128x128, BK=32, 256 threads = 8 warps (2m x 4n), warp tile 64x32.
// ---------------------------------------------------------------------------
#define BM 128
#define BN 128
#define BK 32
#define KSTRIDE 40
#define A_E      0
#define B_E      5120
#define STAGE_E  10240
#define SMEM_BYTES (2 * STAGE_E * 2)      // 40960

__device__ __forceinline__ void cp_async16(uint32_t dst, const void* src)
{
    asm volatile("cp.async.cg.shared.global [%0], [%1], 16;\n"
                 :: "r"(dst), "l"(src));
}
__device__ __forceinline__ void cp_commit() { asm volatile("cp.async.commit_group;\n"); }
__device__ __forceinline__ void cp_wait0()  { asm volatile("cp.async.wait_group 0;\n"); }

#define LDSM_X4(r0, r1, r2, r3, addr) \
    asm volatile("ldmatrix.sync.aligned.m8n8.x4.shared.b16 {%0,%1,%2,%3}, [%4];" \
                 : "=r"(r0), "=r"(r1), "=r"(r2), "=r"(r3) : "r"(addr))

#define STS128(addr, r0, r1, r2, r3) \
    asm volatile("st.shared.v4.b32 [%0], {%1,%2,%3,%4};" \
                 :: "r"(addr), "r"(r0), "r"(r1), "r"(r2), "r"(r3) : "memory")

__device__ __forceinline__ void mma_f16(float c[4], const uint32_t a[4],
                                        const uint32_t b[2])
{
    asm volatile(
        "mma.sync.aligned.m16n8k16.row.col.f32.f16.f16.f32 "
        "{%0,%1,%2,%3}, {%4,%5,%6,%7}, {%8,%9}, {%0,%1,%2,%3};\n"
        : "+f"(c[0]), "+f"(c[1]), "+f"(c[2]), "+f"(c[3])
        : "r"(a[0]), "r"(a[1]), "r"(a[2]), "r"(a[3]), "r"(b[0]), "r"(b[1]));
}

__device__ __forceinline__ uint32_t pack_h2(float a, float b)
{
    __half2 t = __floats2half2_rn(a, b);
    return *reinterpret_cast<uint32_t*>(&t);
}

__global__ __launch_bounds__(256) void gemm_tc_kernel(const float* __restrict__ X)
{
    extern __shared__ __half smem[];
    const int tid  = threadIdx.x;
    const int lane = tid & 31;
    const int wid  = tid >> 5;
    const int wm   = (wid & 1) * 64;
    const int wn   = (wid >> 1) * 32;
    const int m0   = blockIdx.y * BM;
    const int n0   = blockIdx.x * BN;
    const int grp  = lane >> 2;
    const int tig  = lane & 3;

    const uint32_t smem_u32 = (uint32_t)__cvta_generic_to_shared(smem);

    float acc[4][4][4];
#pragma unroll
    for (int mi = 0; mi < 4; mi++)
#pragma unroll
        for (int ni = 0; ni < 4; ni++)
#pragma unroll
            for (int q = 0; q < 4; q++) acc[mi][ni][q] = 0.f;

    const int rowA  = tid >> 1;
    const int halfA = tid & 1;
    int gmA = m0 + rowA;
    if (gmA >= M_NODES) gmA = 0;
    const float* Xrow = X + (size_t)gmA * K_IN + halfA * 16;

    auto ldg_A = [&](int k0, float4 v[4]) {
        const float4* p = reinterpret_cast<const float4*>(Xrow + k0);
        v[0] = __ldg(p);
        v[1] = __ldg(p + 1);
        v[2] = __ldg(p + 2);
        v[3] = __ldg(p + 3);
    };

    auto sts_A = [&](int buf, const float4 v[4]) {
        uint32_t h[8];
#pragma unroll
        for (int j = 0; j < 4; j++) {
            h[2 * j]     = pack_h2(v[j].x, v[j].y);
            h[2 * j + 1] = pack_h2(v[j].z, v[j].w);
        }
        uint32_t base = smem_u32 +
            (uint32_t)(buf * STAGE_E + rowA * KSTRIDE + halfA * 16) * 2;
        STS128(base,      h[0], h[1], h[2], h[3]);
        STS128(base + 16, h[4], h[5], h[6], h[7]);
    };

    auto load_B = [&](int buf, int k0) {
        uint32_t sbase = smem_u32 + (uint32_t)(buf * STAGE_E) * 2;
#pragma unroll
        for (int rep = 0; rep < 2; rep++) {
            int task = tid + rep * 256;
            int row  = task >> 2;
            int ch   = task & 3;
            int gn   = n0 + row;
            uint32_t dB = sbase + (uint32_t)(B_E + row * KSTRIDE + ch * 8) * 2;
            cp_async16(dB, &g_wh[(size_t)gn * K_IN + k0 + ch * 8]);
        }
        cp_commit();
    };

    float4 av[4];
    ldg_A(0, av);
    load_B(0, 0);
    sts_A(0, av);
    ldg_A(BK, av);

    const int a_row = wm + ((lane >> 3) & 1) * 8 + (lane & 7);
    const int a_seg = (lane >> 4) * 8;
    const int b_row = wn + (lane >> 4) * 8 + (lane & 7);
    const int b_seg = ((lane >> 3) & 1) * 8;

    const int NT = K_IN / BK;
    for (int t = 0; t < NT; t++) {
        cp_wait0();
        __syncthreads();

        if (t + 1 < NT) {
            sts_A((t + 1) & 1, av);
            load_B((t + 1) & 1, (t + 1) * BK);
            if (t + 2 < NT) ldg_A((t + 2) * BK, av);
        }

        const uint32_t sbase = smem_u32 + (uint32_t)((t & 1) * STAGE_E) * 2;

#pragma unroll
        for (int ks = 0; ks < 2; ks++) {
            const int kcol = ks * 16;

            uint32_t a[4][4];
#pragma unroll
            for (int mi = 0; mi < 4; mi++) {
                uint32_t addr = sbase + (uint32_t)((a_row + mi * 16) * KSTRIDE + a_seg + kcol) * 2;
                LDSM_X4(a[mi][0], a[mi][1], a[mi][2], a[mi][3], addr);
            }
            uint32_t b[4][2];
#pragma unroll
            for (int njp = 0; njp < 2; njp++) {
                uint32_t addr = sbase + (uint32_t)(B_E + (b_row + njp * 16) * KSTRIDE + b_seg + kcol) * 2;
                LDSM_X4(b[njp * 2][0], b[njp * 2][1],
                        b[njp * 2 + 1][0], b[njp * 2 + 1][1], addr);
            }
#pragma unroll
            for (int mi = 0; mi < 4; mi++)
#pragma unroll
                for (int nj = 0; nj < 4; nj++)
                    mma_f16(acc[mi][nj], a[mi], b[nj]);
        }
    }

    // --- epilogue: fp32 acc -> fp16 x_fts ---
#pragma unroll
    for (int mi = 0; mi < 4; mi++) {
        int gm = m0 + wm + mi * 16 + grp;
#pragma unroll
        for (int nj = 0; nj < 4; nj++) {
            int gn = n0 + wn + nj * 8 + tig * 2;
            if (gm < M_NODES) {
                __half2 h = __float22half2_rn(make_float2(acc[mi][nj][0], acc[mi][nj][1]));
                *reinterpret_cast<__half2*>(&g_xfts_h[(size_t)gm * N_HID + gn]) = h;
            }
            if (gm + 8 < M_NODES) {
                __half2 h = __float22half2_rn(make_float2(acc[mi][nj][2], acc[mi][nj][3]));
                *reinterpret_cast<__half2*>(&g_xfts_h[(size_t)(gm + 8) * N_HID + gn]) = h;
            }
        }
    }
}

// ---------------------------------------------------------------------------
// SPMM + bias + PReLU: 2 rows/CTA, 64 threads/row, one LDG.128 per edge-thread,
// HFMA2 half2 accumulation (4 independent half2x4 accumulators), fp32 finish.
// ---------------------------------------------------------------------------
__global__ __launch_bounds__(128) void spmm_bias_prelu_kernel(
    const float* __restrict__ adj_vals,
    const int* __restrict__ adj_col,
    const float* __restrict__ bias,
    const float* __restrict__ prelu_a,
    float* __restrict__ out)
{
    const int sub = threadIdx.x >> 6;
    const int lt  = threadIdx.x & 63;
    const int r   = blockIdx.x * 2 + sub;
    const int c   = lt * 8;
    const int start = g_rowptr[r];
    const int end   = g_rowptr[r + 1];

    __half2 acc[4][4];
#pragma unroll
    for (int q = 0; q < 4; q++)
#pragma unroll
        for (int j = 0; j < 4; j++)
            acc[q][j] = __half2half2(__ushort_as_half(0));

    auto gather = [&](int e, __half2 f[4]) {
        const int col = __ldg(&adj_col[e]);
        uint4 u = __ldg(reinterpret_cast<const uint4*>(
            &g_xfts_h[(size_t)col * N_HID + c]));
        f[0] = *reinterpret_cast<__half2*>(&u.x);
        f[1] = *reinterpret_cast<__half2*>(&u.y);
        f[2] = *reinterpret_cast<__half2*>(&u.z);
        f[3] = *reinterpret_cast<__half2*>(&u.w);
    };

    int e = start;
    for (; e + 3 < end; e += 4) {
        __half2 v[4];
#pragma unroll
        for (int q = 0; q < 4; q++)
            v[q] = __half2half2(__float2half_rn(__ldg(&adj_vals[e + q])));
        __half2 f[4][4];
#pragma unroll
        for (int q = 0; q < 4; q++) gather(e + q, f[q]);
#pragma unroll
        for (int q = 0; q < 4; q++)
#pragma unroll
            for (int j = 0; j < 4; j++)
                acc[q][j] = __hfma2(v[q], f[q][j], acc[q][j]);
    }
    for (; e < end; e++) {
        __half2 v0 = __half2half2(__float2half_rn(__ldg(&adj_vals[e])));
        __half2 f[4];
        gather(e, f);
#pragma unroll
        for (int j = 0; j < 4; j++)
            acc[0][j] = __hfma2(v0, f[j], acc[0][j]);
    }

    // fp32 finish: sum the 4 accumulators per channel pair
    float o[8];
#pragma unroll
    for (int j = 0; j < 4; j++) {
        float2 s0 = __half22float2(acc[0][j]);
        float2 s1 = __half22float2(acc[1][j]);
        float2 s2 = __half22float2(acc[2][j]);
        float2 s3 = __half22float2(acc[3][j]);
        o[2 * j]     = (s0.x + s1.x) + (s2.x + s3.x);
        o[2 * j + 1] = (s0.y + s1.y) + (s2.y + s3.y);
    }

    const float4 b0 = *reinterpret_cast<const float4*>(&bias[c]);
    const float4 b1 = *reinterpret_cast<const float4*>(&bias[c + 4]);
    const float a = *prelu_a;
    o[0] += b0.x; o[1] += b0.y; o[2] += b0.z; o[3] += b0.w;
    o[4] += b1.x; o[5] += b1.y; o[6] += b1.z; o[7] += b1.w;
#pragma unroll
    for (int j = 0; j < 8; j++)
        o[j] = (o[j] >= 0.f) ? o[j] : a * o[j];

    float* dst = &out[(size_t)r * N_HID + c];
    *reinterpret_cast<float4*>(dst)     = make_float4(o[0], o[1], o[2], o[3]);
    *reinterpret_cast<float4*>(dst + 4) = make_float4(o[4], o[5], o[6], o[7]);
}

extern "C" void kernel_launch(void* const* d_in, const int* in_sizes, int n_in,
                              void* d_out, int out_size)
{
    const float* x        = (const float*)d_in[0];
    const float* fc_w     = (const float*)d_in[1];
    const float* bias     = (const float*)d_in[2];
    const float* prelu_a  = (const float*)d_in[3];
    const float* adj_vals = (const float*)d_in[4];
    const int*   adj_row  = (const int*)d_in[5];
    const int*   adj_col  = (const int*)d_in[6];
    float*       out      = (float*)d_out;

    cudaFuncSetAttribute(gemm_tc_kernel,
                         cudaFuncAttributeMaxDynamicSharedMemorySize, SMEM_BYTES);

    prep_kernel<<<WBLK + RPBLK, 256>>>(fc_w, adj_row);

    dim3 ggrid(N_HID / BN, (M_NODES + BM - 1) / BM);   // 4 x 79
    gemm_tc_kernel<<<ggrid, 256, SMEM_BYTES>>>(x);

    spmm_bias_prelu_kernel<<<M_NODES / 2, 128>>>(adj_vals, adj_col, bias, prelu_a, out);
}